// round 10
// baseline (speedup 1.0000x reference)
#include <cuda_runtime.h>
#include <cstdint>

// Unpool (max_pool_with_argmax inverse), B=16,H=64,W=64,C=128, pool 2x2.
// mask value == flat output index (batch offset included). Input-centric:
// one thread per input float4 reads val+mask once, writes the 2x2 pooled
// output positions {o, o+DW, o+DH, o+DH+DW} (DW=C=128, DH=W2*C=16384).
// All loads and all 4 stores fully coalesced; the 4 stores across all
// threads tile the output exactly once (poisoned buffer fully overwritten).
// Traffic = 32MB val + 64MB mask(i64)/32MB(i32) + 128MB out — minimal.

__device__ int g_mask_is64;

// Detect mask dtype on-device (JAX emits int32 unless x64 is enabled; no
// sync copies allowed under graph capture, and in_sizes[] carries element
// counts, not bytes, so dtype is not host-observable). int64 values < 2^31
// => every odd 32-bit word of the first elements is 0. int32: odd element k
// has c = k&127 odd => that word is odd (nonzero). Any nonzero odd word
// => int32.
__global__ void detect_mask_dtype(const unsigned* __restrict__ mw) {
    int is64 = 1;
#pragma unroll
    for (int k = 1; k < 64; k += 2) {
        if (mw[k] != 0u) { is64 = 0; break; }
    }
    g_mask_is64 = is64;
}

__global__ void __launch_bounds__(256, 4)
unpool_scatter4_kernel(const float4* __restrict__ val4,
                       const void* __restrict__ mask_raw,
                       float4* __restrict__ out4,
                       int n4in)  // number of input float4s (2,097,152)
{
    int t = blockIdx.x * blockDim.x + threadIdx.x;
    if (t >= n4in) return;

    unsigned i = (unsigned)t << 2;             // input element index
    unsigned c = i & 127u;
    unsigned w = (i >> 7)  & 63u;
    unsigned h = (i >> 13) & 63u;
    unsigned b =  i >> 19;

    // output base element index for (b, 2h, 2w, c)
    unsigned o = ((((b << 7) + (h << 1)) << 7) + (w << 1));
    o = (o << 7) + c;
    const unsigned DW = 128u;          // +1 in w2
    const unsigned DH = 128u * 128u;   // +1 in h2

    float4 v = val4[t];

    // Per-element delta = mask - o in 32 bits. Valid matches are
    // {0, DW, DH, DH+DW} + k. Nonzero high word (impossible for valid
    // indices) forces a mismatch via sentinel.
    unsigned d0, d1, d2, d3;
    if (g_mask_is64) {
        const uint4* mp = (const uint4*)mask_raw;   // 2 int64 per uint4
        uint4 a  = mp[i >> 1];
        uint4 bq = mp[(i >> 1) + 1];
        d0 = (a.y  == 0u) ? a.x  - o : 0x80000000u;
        d1 = (a.w  == 0u) ? a.z  - o : 0x80000000u;
        d2 = (bq.y == 0u) ? bq.x - o : 0x80000000u;
        d3 = (bq.w == 0u) ? bq.z - o : 0x80000000u;
    } else {
        const uint4* mp = (const uint4*)mask_raw;
        uint4 a = mp[t];
        d0 = a.x - o; d1 = a.y - o; d2 = a.z - o; d3 = a.w - o;
    }

    float4 r;
    // position 0: delta == k
    r.x = (d0 == 0u) ? v.x : 0.0f;
    r.y = (d1 == 1u) ? v.y : 0.0f;
    r.z = (d2 == 2u) ? v.z : 0.0f;
    r.w = (d3 == 3u) ? v.w : 0.0f;
    __stcs(&out4[o >> 2], r);

    // position 1: delta == DW + k
    r.x = (d0 == DW)      ? v.x : 0.0f;
    r.y = (d1 == DW + 1u) ? v.y : 0.0f;
    r.z = (d2 == DW + 2u) ? v.z : 0.0f;
    r.w = (d3 == DW + 3u) ? v.w : 0.0f;
    __stcs(&out4[(o + DW) >> 2], r);

    // position 2: delta == DH + k
    r.x = (d0 == DH)      ? v.x : 0.0f;
    r.y = (d1 == DH + 1u) ? v.y : 0.0f;
    r.z = (d2 == DH + 2u) ? v.z : 0.0f;
    r.w = (d3 == DH + 3u) ? v.w : 0.0f;
    __stcs(&out4[(o + DH) >> 2], r);

    // position 3: delta == DH + DW + k
    r.x = (d0 == DH + DW)      ? v.x : 0.0f;
    r.y = (d1 == DH + DW + 1u) ? v.y : 0.0f;
    r.z = (d2 == DH + DW + 2u) ? v.z : 0.0f;
    r.w = (d3 == DH + DW + 3u) ? v.w : 0.0f;
    __stcs(&out4[(o + DH + DW) >> 2], r);
}

extern "C" void kernel_launch(void* const* d_in, const int* in_sizes, int n_in,
                              void* d_out, int out_size)
{
    const float* val  = (const float*)d_in[0];
    const void*  mask = (const void*)d_in[1];

    detect_mask_dtype<<<1, 1>>>((const unsigned*)mask);

    int n4in = in_sizes[0] >> 2;   // 8,388,608 / 4 = 2,097,152
    int threads = 256;
    int blocks = (n4in + threads - 1) / threads;
    unpool_scatter4_kernel<<<blocks, threads>>>((const float4*)val, mask,
                                                (float4*)d_out, n4in);
}

// round 13
// speedup vs baseline: 1.0672x; 1.0672x over previous
#include <cuda_runtime.h>
#include <cstdint>

// Unpool (max_pool_with_argmax inverse), B=16,H=64,W=64,C=128, pool 2x2.
// mask value == flat output index (batch offset included). Input-centric:
// each thread handles TWO input float4s (t and t+half), reads val+mask once,
// writes the 2x2 pooled output positions {o, o+DW, o+DH, o+DH+DW}
// (DW=C=128 elems, DH=W2*C=16384 elems). All loads and stores coalesced;
// stores tile the 128MB output exactly once. Mask dtype (i32 vs i64, JAX
// x64-dependent) is detected in-kernel from one uniform probe word:
// int64 => word[1] (high word of elem 0) == 0; int32 => word[1] odd.

__device__ __forceinline__ void emit(float4* __restrict__ out4, unsigned t,
                                     float4 v,
                                     unsigned m0, unsigned m1,
                                     unsigned m2, unsigned m3)
{
    unsigned i = t << 2;                 // input element index
    unsigned c = i & 127u;
    unsigned w = (i >> 7)  & 63u;
    unsigned h = (i >> 13) & 63u;
    unsigned b =  i >> 19;

    // output base element index for (b, 2h, 2w, c)
    unsigned o = ((((b << 7) + (h << 1)) << 7) + (w << 1));
    o = (o << 7) + c;
    const unsigned DW = 128u;            // +1 in w2
    const unsigned DH = 128u * 128u;     // +1 in h2

    // delta = mask - o; valid matches are {0, DW, DH, DH+DW} + k.
    // Sentinel masks (>= 2^31) give deltas far outside that set.
    unsigned d0 = m0 - o, d1 = m1 - o, d2 = m2 - o, d3 = m3 - o;

    float4 r;
    r.x = (d0 == 0u) ? v.x : 0.0f;
    r.y = (d1 == 1u) ? v.y : 0.0f;
    r.z = (d2 == 2u) ? v.z : 0.0f;
    r.w = (d3 == 3u) ? v.w : 0.0f;
    __stcs(&out4[o >> 2], r);

    r.x = (d0 == DW)      ? v.x : 0.0f;
    r.y = (d1 == DW + 1u) ? v.y : 0.0f;
    r.z = (d2 == DW + 2u) ? v.z : 0.0f;
    r.w = (d3 == DW + 3u) ? v.w : 0.0f;
    __stcs(&out4[(o + DW) >> 2], r);

    r.x = (d0 == DH)      ? v.x : 0.0f;
    r.y = (d1 == DH + 1u) ? v.y : 0.0f;
    r.z = (d2 == DH + 2u) ? v.z : 0.0f;
    r.w = (d3 == DH + 3u) ? v.w : 0.0f;
    __stcs(&out4[(o + DH) >> 2], r);

    r.x = (d0 == DH + DW)      ? v.x : 0.0f;
    r.y = (d1 == DH + DW + 1u) ? v.y : 0.0f;
    r.z = (d2 == DH + DW + 2u) ? v.z : 0.0f;
    r.w = (d3 == DH + DW + 3u) ? v.w : 0.0f;
    __stcs(&out4[(o + DH + DW) >> 2], r);
}

__global__ void __launch_bounds__(256, 4)
unpool_scatter4x2_kernel(const float4* __restrict__ val4,
                         const unsigned* __restrict__ mask_w,
                         float4* __restrict__ out4,
                         int half)  // n4in/2 = 1,048,576
{
    int t = blockIdx.x * blockDim.x + threadIdx.x;
    if (t >= half) return;
    unsigned t0 = (unsigned)t;
    unsigned t1 = t0 + (unsigned)half;

    // Uniform dtype probe: one word, same address chip-wide (L2 broadcast).
    bool is64 = (mask_w[1] == 0u);

    float4 v0 = val4[t0];
    float4 v1 = val4[t1];

    const unsigned SENT = 0x80000000u;   // >= 2^31: can never match

    if (is64) {
        const uint4* mp = (const uint4*)mask_w;   // 2 int64 per uint4
        unsigned i0 = t0 << 2, i1 = t1 << 2;
        uint4 a0 = mp[i0 >> 1];
        uint4 b0 = mp[(i0 >> 1) + 1];
        uint4 a1 = mp[i1 >> 1];
        uint4 b1 = mp[(i1 >> 1) + 1];
        emit(out4, t0, v0,
             (a0.y == 0u) ? a0.x : SENT, (a0.w == 0u) ? a0.z : SENT,
             (b0.y == 0u) ? b0.x : SENT, (b0.w == 0u) ? b0.z : SENT);
        emit(out4, t1, v1,
             (a1.y == 0u) ? a1.x : SENT, (a1.w == 0u) ? a1.z : SENT,
             (b1.y == 0u) ? b1.x : SENT, (b1.w == 0u) ? b1.z : SENT);
    } else {
        const uint4* mp = (const uint4*)mask_w;
        uint4 m0 = mp[t0];
        uint4 m1 = mp[t1];
        emit(out4, t0, v0, m0.x, m0.y, m0.z, m0.w);
        emit(out4, t1, v1, m1.x, m1.y, m1.z, m1.w);
    }
}

extern "C" void kernel_launch(void* const* d_in, const int* in_sizes, int n_in,
                              void* d_out, int out_size)
{
    const float*    val  = (const float*)d_in[0];
    const unsigned* mask = (const unsigned*)d_in[1];

    int n4in = in_sizes[0] >> 2;   // 2,097,152 input float4s
    int half = n4in >> 1;          // 1,048,576 threads, 2 float4s each
    int threads = 256;
    int blocks = (half + threads - 1) / threads;
    unpool_scatter4x2_kernel<<<blocks, threads>>>((const float4*)val, mask,
                                                  (float4*)d_out, half);
}